// round 2
// baseline (speedup 1.0000x reference)
#include <cuda_runtime.h>
#include <cuda_bf16.h>

// SVD recommender predict:
//   predict[b]  = clip(gm + bu[uid] + bi[iid] + dot(pu[uid], qi[iid]), 1, 5)
//   feat[b,:64] = pu[uid], feat[b,64:128] = qi[iid]
// Output layout: d_out[0:B] = predict, d_out[B : B + B*128] = features row-major.
//
// 16 lanes per batch element: each lane does one float4 load from pu-row and
// one from qi-row (64 floats = 16 x float4), dot reduced via shfl_xor within
// the 16-lane group, features written back as float4 (2x STG.128 per lane).

#define N_FACTORS 64
#define BATCH     131072

__global__ __launch_bounds__(256) void svd_predict_kernel(
    const int2*   __restrict__ user_item,   // [BATCH] pairs (uid, iid)
    const float4* __restrict__ pu,          // [N_USERS * 16] float4
    const float4* __restrict__ qi,          // [N_ITEMS * 16] float4
    const float*  __restrict__ bu,
    const float*  __restrict__ bi,
    const float*  __restrict__ gmean,       // scalar on device
    float*        __restrict__ out_pred,    // [BATCH]
    float4*       __restrict__ out_feat)    // [BATCH * 32] float4
{
    const int tid  = blockIdx.x * blockDim.x + threadIdx.x;
    const int elem = tid >> 4;          // batch element
    const int lane = tid & 15;          // lane within 16-lane group
    if (elem >= BATCH) return;

    const int2 ui = user_item[elem];
    const int uid = ui.x;
    const int iid = ui.y;

    // Gather: each row is 64 floats = 16 float4 = 2 x 128B lines, fully used.
    const float4 p = pu[(size_t)uid * (N_FACTORS / 4) + lane];
    const float4 q = qi[(size_t)iid * (N_FACTORS / 4) + lane];

    float dot = p.x * q.x + p.y * q.y + p.z * q.z + p.w * q.w;

    // Reduce across the 16-lane group (xor offsets stay within the group).
    #pragma unroll
    for (int off = 8; off > 0; off >>= 1)
        dot += __shfl_xor_sync(0xffffffffu, dot, off);

    // Feature row: 128 floats = 32 float4. p goes to [0:16), q to [16:32).
    float4* frow = out_feat + (size_t)elem * (2 * N_FACTORS / 4);
    frow[lane]      = p;
    frow[16 + lane] = q;

    if (lane == 0) {
        float pr = gmean[0] + bu[uid] + bi[iid] + dot;
        pr = fminf(fmaxf(pr, 1.0f), 5.0f);
        out_pred[elem] = pr;
    }
}

extern "C" void kernel_launch(void* const* d_in, const int* in_sizes, int n_in,
                              void* d_out, int out_size)
{
    // metadata order: user_item(int32), pu(f32), qi(f32), bu(f32), bi(f32), global_mean(f32)
    const int2*   user_item = (const int2*)  d_in[0];
    const float4* pu        = (const float4*)d_in[1];
    const float4* qi        = (const float4*)d_in[2];
    const float*  bu        = (const float*) d_in[3];
    const float*  bi        = (const float*) d_in[4];
    const float*  gmean     = (const float*) d_in[5];

    float*  out_pred = (float*)d_out;
    float4* out_feat = (float4*)((float*)d_out + BATCH);

    // 16 threads per element, 256 threads/block -> 16 elements/block
    const int threads = 256;
    const int blocks  = (BATCH * 16) / threads;   // 8192
    svd_predict_kernel<<<blocks, threads>>>(user_item, pu, qi, bu, bi, gmean,
                                            out_pred, out_feat);
}

// round 6
// speedup vs baseline: 1.1731x; 1.1731x over previous
#include <cuda_runtime.h>
#include <cuda_bf16.h>

// SVD recommender predict:
//   predict[b]  = clip(gm + bu[uid] + bi[iid] + dot(pu[uid], qi[iid]), 1, 5)
//   feat[b,:64] = pu[uid], feat[b,64:128] = qi[iid]
// Output layout: d_out[0:B] = predict, d_out[B : B + B*128] = features row-major.
//
// 4 lanes per batch element: each lane loads 4 independent float4 from the
// pu-row and 4 from the qi-row (MLP=8 gather loads in flight per thread),
// dot reduced over the 4-lane group with 2 shfl_xor. Streaming stores use
// .cs (evict-first) so the 67MB write stream doesn't thrash L2.

#define N_FACTORS 64
#define BATCH     131072

__global__ __launch_bounds__(256) void svd_predict_kernel(
    const int2*   __restrict__ user_item,   // [BATCH] (uid, iid)
    const float4* __restrict__ pu,          // [N_USERS * 16] float4
    const float4* __restrict__ qi,          // [N_ITEMS * 16] float4
    const float*  __restrict__ bu,
    const float*  __restrict__ bi,
    const float*  __restrict__ gmean,
    float*        __restrict__ out_pred,    // [BATCH]
    float4*       __restrict__ out_feat)    // [BATCH * 32] float4
{
    const int tid  = blockIdx.x * blockDim.x + threadIdx.x;
    const int elem = tid >> 2;          // batch element
    const int lane = tid & 3;           // lane within 4-lane group
    if (elem >= BATCH) return;

    const int2 ui = user_item[elem];
    const int uid = ui.x;
    const int iid = ui.y;

    const float4* __restrict__ prow = pu + (size_t)uid * (N_FACTORS / 4);
    const float4* __restrict__ qrow = qi + (size_t)iid * (N_FACTORS / 4);

    // 8 independent 128-bit gathers per thread; lanes 0-3 cover 64B chunks.
    float4 p[4], q[4];
    #pragma unroll
    for (int j = 0; j < 4; j++) p[j] = prow[lane + 4 * j];
    #pragma unroll
    for (int j = 0; j < 4; j++) q[j] = qrow[lane + 4 * j];

    float dot = 0.0f;
    #pragma unroll
    for (int j = 0; j < 4; j++) {
        dot += p[j].x * q[j].x;
        dot += p[j].y * q[j].y;
        dot += p[j].z * q[j].z;
        dot += p[j].w * q[j].w;
    }
    // Reduce over the 4-lane group.
    dot += __shfl_xor_sync(0xffffffffu, dot, 2);
    dot += __shfl_xor_sync(0xffffffffu, dot, 1);

    // Feature row: 128 floats = 32 float4. Streaming (evict-first) stores.
    float4* frow = out_feat + (size_t)elem * (2 * N_FACTORS / 4);
    #pragma unroll
    for (int j = 0; j < 4; j++) __stcs(frow + lane + 4 * j, p[j]);
    #pragma unroll
    for (int j = 0; j < 4; j++) __stcs(frow + 16 + lane + 4 * j, q[j]);

    if (lane == 0) {
        float pr = gmean[0] + bu[uid] + bi[iid] + dot;
        pr = fminf(fmaxf(pr, 1.0f), 5.0f);
        __stcs(out_pred + elem, pr);
    }
}

extern "C" void kernel_launch(void* const* d_in, const int* in_sizes, int n_in,
                              void* d_out, int out_size)
{
    const int2*   user_item = (const int2*)  d_in[0];
    const float4* pu        = (const float4*)d_in[1];
    const float4* qi        = (const float4*)d_in[2];
    const float*  bu        = (const float*) d_in[3];
    const float*  bi        = (const float*) d_in[4];
    const float*  gmean     = (const float*) d_in[5];

    float*  out_pred = (float*)d_out;
    float4* out_feat = (float4*)((float*)d_out + BATCH);

    // 4 threads per element, 256 threads/block
    const int threads = 256;
    const int blocks  = (BATCH * 4) / threads;   // 2048
    svd_predict_kernel<<<blocks, threads>>>(user_item, pu, qi, bu, bi, gmean,
                                            out_pred, out_feat);
}